// round 6
// baseline (speedup 1.0000x reference)
#include <cuda_runtime.h>
#include <cuda_bf16.h>
#include <cstdint>

#define BATCH 8
#define CCH   256
#define WID   4096
#define NT    64      // j tiles of 64
#define CT    4       // channel tiles of 64

// pre-split bf16 operands
__device__ __nv_bfloat16 g_xh[(size_t)BATCH * CCH * WID];
__device__ __nv_bfloat16 g_xl[(size_t)BATCH * CCH * WID];
__device__ __nv_bfloat16 g_wh[(size_t)3 * CCH * CCH];
__device__ __nv_bfloat16 g_wl[(size_t)3 * CCH * CCH];
// edge scratch for cross-tile windows
__device__ float g_q_edge[(size_t)BATCH * CCH * NT * 6];
__device__ float g_kv_edge[(size_t)BATCH * CCH * NT * 24];  // 12 k + 12 v

// ---------------------------------------------------------------------------
__device__ __forceinline__ uint32_t sptr(const void* p) {
    return (uint32_t)__cvta_generic_to_shared(p);
}
__device__ __forceinline__ void split2(float f0, float f1, uint32_t& h, uint32_t& l) {
    __nv_bfloat16 h0 = __float2bfloat16(f0);
    __nv_bfloat16 h1 = __float2bfloat16(f1);
    __nv_bfloat16 l0 = __float2bfloat16(f0 - __bfloat162float(h0));
    __nv_bfloat16 l1 = __float2bfloat16(f1 - __bfloat162float(h1));
    h = (uint32_t)__bfloat16_as_ushort(h0) | ((uint32_t)__bfloat16_as_ushort(h1) << 16);
    l = (uint32_t)__bfloat16_as_ushort(l0) | ((uint32_t)__bfloat16_as_ushort(l1) << 16);
}
__device__ __forceinline__ void ldsm_x4(uint32_t addr, uint32_t* r) {
    asm volatile("ldmatrix.sync.aligned.m8n8.x4.shared.b16 {%0,%1,%2,%3}, [%4];"
                 : "=r"(r[0]), "=r"(r[1]), "=r"(r[2]), "=r"(r[3]) : "r"(addr));
}
__device__ __forceinline__ void ldsm_x4_t(uint32_t addr, uint32_t& r0, uint32_t& r1,
                                          uint32_t& r2, uint32_t& r3) {
    asm volatile("ldmatrix.sync.aligned.m8n8.x4.trans.shared.b16 {%0,%1,%2,%3}, [%4];"
                 : "=r"(r0), "=r"(r1), "=r"(r2), "=r"(r3) : "r"(addr));
}
__device__ __forceinline__ void mma16816(float* c, const uint32_t* a,
                                         uint32_t b0, uint32_t b1) {
    asm volatile(
        "mma.sync.aligned.m16n8k16.row.col.f32.bf16.bf16.f32 "
        "{%0,%1,%2,%3}, {%4,%5,%6,%7}, {%8,%9}, {%0,%1,%2,%3};"
        : "+f"(c[0]), "+f"(c[1]), "+f"(c[2]), "+f"(c[3])
        : "r"(a[0]), "r"(a[1]), "r"(a[2]), "r"(a[3]), "r"(b0), "r"(b1));
}
#define CP16(dst, src) \
    asm volatile("cp.async.cg.shared.global [%0], [%1], 16;" :: "r"(dst), "l"(src))
#define CP_COMMIT() asm volatile("cp.async.commit_group;")
#define CP_WAIT(n)  asm volatile("cp.async.wait_group %0;" :: "n"(n))

// ---------------------------------------------------------------------------
// Kernel 0: split fp32 -> bf16 hi/lo
// ---------------------------------------------------------------------------
#define NX4 (BATCH * CCH * WID / 4)
#define NW4 (CCH * CCH / 4)

__global__ __launch_bounds__(256)
void convert_split(const float* __restrict__ x, const float* __restrict__ wq,
                   const float* __restrict__ wk, const float* __restrict__ wv)
{
    int idx = blockIdx.x * 256 + threadIdx.x;
    if (idx < NX4) {
        float4 v = ((const float4*)x)[idx];
        uint32_t h01, l01, h23, l23;
        split2(v.x, v.y, h01, l01);
        split2(v.z, v.w, h23, l23);
        ((uint2*)g_xh)[idx] = make_uint2(h01, h23);
        ((uint2*)g_xl)[idx] = make_uint2(l01, l23);
    } else {
        int r = idx - NX4;
        if (r < 3 * NW4) {
            int g = r / NW4, e = r % NW4;
            const float* W = (g == 0) ? wq : (g == 1) ? wk : wv;
            float4 v = ((const float4*)W)[e];
            uint32_t h01, l01, h23, l23;
            split2(v.x, v.y, h01, l01);
            split2(v.z, v.w, h23, l23);
            ((uint2*)g_wh)[g * NW4 + e] = make_uint2(h01, h23);
            ((uint2*)g_wl)[g * NW4 + e] = make_uint2(l01, l23);
        }
    }
}

// ---------------------------------------------------------------------------
// Fused kernel: CTA computes q,k,v (M=192 = 3 groups x 64 ch) x (N=64 j),
// then windowed softmax in-SMEM, writing out + edge scratch.
// Stage layout (39936 B): Ah[192][40]@0, Al@15360, Bh[32][72]@30720, Bl@35328
// Epilogue planes (aliased at 0): q/k/v [64][67] f32, 17152 B each.
// ---------------------------------------------------------------------------
#define STAGE_BYTES 39936
#define SMEM_FUSED  (2 * STAGE_BYTES)   // 79872
#define PLANE       (64 * 67)

__device__ __forceinline__ void prefetch(char* s, int stage, int tid,
                                         int c0, int kc,
                                         const __nv_bfloat16* __restrict__ xhb,
                                         const __nv_bfloat16* __restrict__ xlb,
                                         int j0)
{
    uint32_t base = sptr(s + stage * STAGE_BYTES);
    #pragma unroll
    for (int i = 0; i < 3; ++i) {
        int e = tid + i * 256;
        int row = e >> 2, seg = e & 3;
        size_t src = (size_t)(row >> 6) * (CCH * CCH)
                   + (size_t)(c0 + (row & 63)) * CCH + kc + seg * 8;
        uint32_t off = (uint32_t)(row * 40 + seg * 8) * 2;
        CP16(base + off,         g_wh + src);
        CP16(base + 15360 + off, g_wl + src);
    }
    {
        int row = tid >> 3, seg = tid & 7;
        size_t src = (size_t)(kc + row) * WID + j0 + seg * 8;
        uint32_t off = (uint32_t)(row * 72 + seg * 8) * 2;
        CP16(base + 30720 + off, xhb + src);
        CP16(base + 35328 + off, xlb + src);
    }
}

__global__ __launch_bounds__(256, 2)
void fused_qkv_attn(float* __restrict__ out)
{
    extern __shared__ char smem[];

    const int nt = blockIdx.x;     // 0..63
    const int ct = blockIdx.y;     // 0..3
    const int b  = blockIdx.z;     // 0..7
    const int j0 = nt * 64;
    const int c0 = ct * 64;

    const __nv_bfloat16* xhb = g_xh + (size_t)b * CCH * WID;
    const __nv_bfloat16* xlb = g_xl + (size_t)b * CCH * WID;

    const int tid  = threadIdx.x;
    const int lane = tid & 31;
    const int wid  = tid >> 5;
    const int wm   = wid >> 1;     // 0..3, 48 rows each
    const int wn   = wid & 1;      // 0..1, 32 cols each
    const int ltt  = lane >> 3;
    const int ltr  = lane & 7;

    float acc[3][4][4];
    #pragma unroll
    for (int i = 0; i < 3; ++i)
        #pragma unroll
        for (int j = 0; j < 4; ++j)
            #pragma unroll
            for (int r = 0; r < 4; ++r) acc[i][j][r] = 0.f;

    prefetch(smem, 0, tid, c0, 0, xhb, xlb, j0);
    CP_COMMIT();

    #pragma unroll 1
    for (int kc8 = 0; kc8 < 8; ++kc8) {
        const int stage = kc8 & 1;
        if (kc8 < 7) {
            prefetch(smem, stage ^ 1, tid, c0, (kc8 + 1) * 32, xhb, xlb, j0);
            CP_COMMIT();
            CP_WAIT(1);
        } else {
            CP_WAIT(0);
        }
        __syncthreads();

        const char* sb = smem + stage * STAGE_BYTES;
        const __nv_bfloat16* Ahp = (const __nv_bfloat16*)(sb);
        const __nv_bfloat16* Alp = (const __nv_bfloat16*)(sb + 15360);
        const __nv_bfloat16* Bhp = (const __nv_bfloat16*)(sb + 30720);
        const __nv_bfloat16* Blp = (const __nv_bfloat16*)(sb + 35328);

        #pragma unroll
        for (int ks = 0; ks < 2; ++ks) {
            const int kb = ks * 16;
            uint32_t bh[4][2], bl[4][2];
            #pragma unroll
            for (int np = 0; np < 2; ++np) {
                int krow = kb + (ltt & 1) * 8 + ltr;
                int ncol = wn * 32 + np * 16 + (ltt >> 1) * 8;
                ldsm_x4_t(sptr(Bhp + krow * 72 + ncol),
                          bh[np * 2][0], bh[np * 2][1],
                          bh[np * 2 + 1][0], bh[np * 2 + 1][1]);
                ldsm_x4_t(sptr(Blp + krow * 72 + ncol),
                          bl[np * 2][0], bl[np * 2][1],
                          bl[np * 2 + 1][0], bl[np * 2 + 1][1]);
            }
            uint32_t ah[3][4], al[3][4];
            #pragma unroll
            for (int ma = 0; ma < 3; ++ma) {
                int row = wm * 48 + ma * 16 + (ltt & 1) * 8 + ltr;
                int col = kb + (ltt >> 1) * 8;
                ldsm_x4(sptr(Ahp + row * 40 + col), ah[ma]);
                ldsm_x4(sptr(Alp + row * 40 + col), al[ma]);
            }
            #pragma unroll
            for (int ma = 0; ma < 3; ++ma)
                #pragma unroll
                for (int na = 0; na < 4; ++na)
                    mma16816(acc[ma][na], ah[ma], bh[na][0], bh[na][1]);
            #pragma unroll
            for (int ma = 0; ma < 3; ++ma)
                #pragma unroll
                for (int na = 0; na < 4; ++na)
                    mma16816(acc[ma][na], al[ma], bh[na][0], bh[na][1]);
            #pragma unroll
            for (int ma = 0; ma < 3; ++ma)
                #pragma unroll
                for (int na = 0; na < 4; ++na)
                    mma16816(acc[ma][na], ah[ma], bl[na][0], bl[na][1]);
        }
        __syncthreads();
    }

    // ---- epilogue: accs -> SMEM planes (q/k/v [64][67] f32 each) ----
    float* Pl = (float*)smem;
    #pragma unroll
    for (int ma = 0; ma < 3; ++ma) {
        int r = wm * 48 + ma * 16 + (lane >> 2);      // atom 16-aligned, never straddles 64
        int jj = wn * 32 + (lane & 3) * 2;
        float* pg = Pl + (r >> 6) * PLANE;
        #pragma unroll
        for (int na = 0; na < 4; ++na) {
            int j2 = jj + na * 8;
            pg[(r & 63) * 67 + j2]       = acc[ma][na][0];
            pg[(r & 63) * 67 + j2 + 1]   = acc[ma][na][1];
            pg[((r + 8) & 63) * 67 + j2]     = acc[ma][na][2];
            pg[((r + 8) & 63) * 67 + j2 + 1] = acc[ma][na][3];
        }
    }
    __syncthreads();

    const float* Pq = Pl;
    const float* Pk = Pl + PLANE;
    const float* Pv = Pl + 2 * PLANE;

    // ---- edge scratch exports ----
    for (int i2 = tid; i2 < 64 * 6; i2 += 256) {
        int c2 = i2 / 6, e = i2 % 6;
        int jl = (e < 3) ? e : e + 58;                 // {0,1,2,61,62,63}
        g_q_edge[(((size_t)(b * 256 + c0 + c2)) * NT + nt) * 6 + e] = Pq[c2 * 67 + jl];
    }
    for (int i2 = tid; i2 < 64 * 12; i2 += 256) {
        int c2 = i2 / 12, ke = i2 % 12;
        int jl = (ke < 6) ? ke : ke + 52;              // {0..5, 58..63}
        size_t base = (((size_t)(b * 256 + c0 + c2)) * NT + nt) * 24;
        g_kv_edge[base + ke]      = Pk[c2 * 67 + jl];
        g_kv_edge[base + 12 + ke] = Pv[c2 * 67 + jl];
    }

    // ---- in-tile attention ----
    const int c  = tid >> 2;
    const int jb = (tid & 3) * 16;
    const float* qr = Pq + c * 67;
    const float* kr = Pk + c * 67;
    const float* vr = Pv + c * 67;
    float* orow = out + (size_t)(b * 256 + c0 + c) * WID + j0;

    #pragma unroll
    for (int q4 = 0; q4 < 4; ++q4) {
        const int jl0 = jb + q4 * 4;
        float res[4];
        bool st[4];
        #pragma unroll
        for (int u = 0; u < 4; ++u) {
            int jl = jl0 + u;
            st[u] = (jl >= 3 || nt == 0) && (jl < 61 || nt == NT - 1);
            res[u] = 0.f;
            if (st[u]) {
                float q = qr[jl];
                float s[7], m = -1e30f;
                #pragma unroll
                for (int d = 0; d < 7; ++d) {
                    int jj = jl + d - 3;
                    float kvk = (jj >= 0 && jj < 64) ? kr[jj] : 0.f;
                    s[d] = q * kvk;
                    m = fmaxf(m, s[d]);
                }
                float sum = 0.f, accn = 0.f;
                #pragma unroll
                for (int d = 0; d < 7; ++d) {
                    int jj = jl + d - 3;
                    float kvv = (jj >= 0 && jj < 64) ? vr[jj] : 0.f;
                    float ee = __expf(s[d] - m);
                    sum  += ee;
                    accn = fmaf(ee, kvv, accn);
                }
                res[u] = accn / sum;
            }
        }
        if (st[0] && st[1] && st[2] && st[3]) {
            *(float4*)(orow + jl0) = make_float4(res[0], res[1], res[2], res[3]);
        } else {
            #pragma unroll
            for (int u = 0; u < 4; ++u)
                if (st[u]) orow[jl0 + u] = res[u];
        }
    }
}

// ---------------------------------------------------------------------------
// Boundary kernel: outputs with (j mod 64) in {0,1,2,61,62,63} at internal
// tile boundaries (a = 1..63).
// ---------------------------------------------------------------------------
#define NBOUND (63 * 6 * BATCH * CCH)   // 774144

__global__ __launch_bounds__(256)
void attn_boundary(float* __restrict__ out)
{
    int idx = blockIdx.x * 256 + threadIdx.x;
    if (idx >= NBOUND) return;
    int e = idx % 6;
    int a = (idx / 6) % 63 + 1;
    int t = idx / (6 * 63);            // b*256 + o

    int j = a * 64 + ((e < 3) ? e : e - 6);
    int tq = j >> 6, jl = j & 63;
    int qe = (jl < 3) ? jl : jl - 58;
    float q = g_q_edge[((size_t)t * NT + tq) * 6 + qe];

    float s[7], vv[7], m = -1e30f;
    #pragma unroll
    for (int d = 0; d < 7; ++d) {
        int jj = j + d - 3;            // a in 1..63 -> always in [58, 4038]
        int td = jj >> 6, loc = jj & 63;
        int ke = (loc < 6) ? loc : loc - 52;
        size_t base = ((size_t)t * NT + td) * 24;
        float kk = g_kv_edge[base + ke];
        vv[d] = g_kv_edge[base + 12 + ke];
        s[d] = q * kk;
        m = fmaxf(m, s[d]);
    }
    float sum = 0.f, accn = 0.f;
    #pragma unroll
    for (int d = 0; d < 7; ++d) {
        float ee = __expf(s[d] - m);
        sum  += ee;
        accn = fmaf(ee, vv[d], accn);
    }
    out[(size_t)t * WID + j] = accn / sum;
}

// ---------------------------------------------------------------------------
extern "C" void kernel_launch(void* const* d_in, const int* in_sizes, int n_in,
                              void* d_out, int out_size)
{
    (void)in_sizes; (void)n_in; (void)out_size;
    const float* x  = (const float*)d_in[0];
    const float* wq = (const float*)d_in[1];
    const float* wk = (const float*)d_in[2];
    const float* wv = (const float*)d_in[3];
    float* out = (float*)d_out;

    cudaFuncSetAttribute(fused_qkv_attn, cudaFuncAttributeMaxDynamicSharedMemorySize, SMEM_FUSED);

    convert_split<<<(NX4 + 3 * NW4 + 255) / 256, 256>>>(x, wq, wk, wv);

    dim3 grid(NT, CT, BATCH);   // 64 x 4 x 8
    fused_qkv_attn<<<grid, 256, SMEM_FUSED>>>(out);

    attn_boundary<<<(NBOUND + 255) / 256, 256>>>(out);
}

// round 7
// speedup vs baseline: 1.0080x; 1.0080x over previous
#include <cuda_runtime.h>
#include <cuda_fp16.h>
#include <cstdint>

#define BATCH 8
#define CCH   256
#define WID   4096
#define GROUPS 3

// fp32 scratch: qkv[g*256+o][b][j]
__device__ float g_qkv[(size_t)GROUPS * CCH * BATCH * WID];
// pre-split fp16 operands
__device__ __half g_xh[(size_t)BATCH * CCH * WID];
__device__ __half g_xl[(size_t)BATCH * CCH * WID];
__device__ __half g_wh[(size_t)GROUPS * CCH * CCH];
__device__ __half g_wl[(size_t)GROUPS * CCH * CCH];

// ---------------------------------------------------------------------------
__device__ __forceinline__ uint32_t sptr(const void* p) {
    return (uint32_t)__cvta_generic_to_shared(p);
}
__device__ __forceinline__ void split2h(float f0, float f1, uint32_t& h, uint32_t& l) {
    __half h0 = __float2half_rn(f0);
    __half h1 = __float2half_rn(f1);
    __half l0 = __float2half_rn(f0 - __half2float(h0));
    __half l1 = __float2half_rn(f1 - __half2float(h1));
    h = (uint32_t)__half_as_ushort(h0) | ((uint32_t)__half_as_ushort(h1) << 16);
    l = (uint32_t)__half_as_ushort(l0) | ((uint32_t)__half_as_ushort(l1) << 16);
}
__device__ __forceinline__ void ldsm_x4(uint32_t addr, uint32_t* r) {
    asm volatile("ldmatrix.sync.aligned.m8n8.x4.shared.b16 {%0,%1,%2,%3}, [%4];"
                 : "=r"(r[0]), "=r"(r[1]), "=r"(r[2]), "=r"(r[3]) : "r"(addr));
}
__device__ __forceinline__ void ldsm_x4_t(uint32_t addr, uint32_t& r0, uint32_t& r1,
                                          uint32_t& r2, uint32_t& r3) {
    asm volatile("ldmatrix.sync.aligned.m8n8.x4.trans.shared.b16 {%0,%1,%2,%3}, [%4];"
                 : "=r"(r0), "=r"(r1), "=r"(r2), "=r"(r3) : "r"(addr));
}
// fp16 inputs, fp32 accumulate (full-rate main pass)
__device__ __forceinline__ void mma_f32(float* c, const uint32_t* a,
                                        uint32_t b0, uint32_t b1) {
    asm volatile(
        "mma.sync.aligned.m16n8k16.row.col.f32.f16.f16.f32 "
        "{%0,%1,%2,%3}, {%4,%5,%6,%7}, {%8,%9}, {%0,%1,%2,%3};"
        : "+f"(c[0]), "+f"(c[1]), "+f"(c[2]), "+f"(c[3])
        : "r"(a[0]), "r"(a[1]), "r"(a[2]), "r"(a[3]), "r"(b0), "r"(b1));
}
// fp16 inputs, fp16 accumulate (2x rate, for the small cross terms)
__device__ __forceinline__ void mma_f16(uint32_t* d, const uint32_t* a,
                                        uint32_t b0, uint32_t b1) {
    asm volatile(
        "mma.sync.aligned.m16n8k16.row.col.f16.f16.f16.f16 "
        "{%0,%1}, {%2,%3,%4,%5}, {%6,%7}, {%0,%1};"
        : "+r"(d[0]), "+r"(d[1])
        : "r"(a[0]), "r"(a[1]), "r"(a[2]), "r"(a[3]), "r"(b0), "r"(b1));
}
#define CP16(dst, src) \
    asm volatile("cp.async.cg.shared.global [%0], [%1], 16;" :: "r"(dst), "l"(src))
#define CP_COMMIT() asm volatile("cp.async.commit_group;")
#define CP_WAIT(n)  asm volatile("cp.async.wait_group %0;" :: "n"(n))

// ---------------------------------------------------------------------------
// Kernel 0: split fp32 -> fp16 hi/lo
// ---------------------------------------------------------------------------
#define NX4 (BATCH * CCH * WID / 4)
#define NW4 (CCH * CCH / 4)

__global__ __launch_bounds__(256)
void convert_split(const float* __restrict__ x, const float* __restrict__ wq,
                   const float* __restrict__ wk, const float* __restrict__ wv)
{
    int idx = blockIdx.x * 256 + threadIdx.x;
    if (idx < NX4) {
        float4 v = ((const float4*)x)[idx];
        uint32_t h01, l01, h23, l23;
        split2h(v.x, v.y, h01, l01);
        split2h(v.z, v.w, h23, l23);
        ((uint2*)g_xh)[idx] = make_uint2(h01, h23);
        ((uint2*)g_xl)[idx] = make_uint2(l01, l23);
    } else {
        int r = idx - NX4;
        if (r < 3 * NW4) {
            int g = r / NW4, e = r % NW4;
            const float* W = (g == 0) ? wq : (g == 1) ? wk : wv;
            float4 v = ((const float4*)W)[e];
            uint32_t h01, l01, h23, l23;
            split2h(v.x, v.y, h01, l01);
            split2h(v.z, v.w, h23, l23);
            ((uint2*)g_wh)[g * NW4 + e] = make_uint2(h01, h23);
            ((uint2*)g_wl)[g * NW4 + e] = make_uint2(l01, l23);
        }
    }
}

// ---------------------------------------------------------------------------
// Kernel 1: GEMM, fp16 split. Main term fp32-acc; cross terms fp16-acc (2x rate).
// CTA tile 128m x 64n, k-chunk 32, 8 warps with 32x32 warp tiles (4m x 2n).
// Stage (29696 B): Ah[128][40]@0, Al@10240, Bh[32][72]@20480, Bl@25088
// ---------------------------------------------------------------------------
#define STAGE_BYTES 29696
#define SMEM_GEMM   (2 * STAGE_BYTES)

__device__ __forceinline__ void prefetch(char* s, int stage, int tid,
                                         const __half* __restrict__ whg,
                                         const __half* __restrict__ wlg,
                                         const __half* __restrict__ xhb,
                                         const __half* __restrict__ xlb,
                                         int kc, int j0)
{
    uint32_t base = sptr(s + stage * STAGE_BYTES);
    #pragma unroll
    for (int i = 0; i < 2; ++i) {
        int e = tid + i * 256;
        int row = e >> 2, seg = e & 3;
        uint32_t off = (uint32_t)(row * 40 + seg * 8) * 2;
        CP16(base + off,         whg + (size_t)row * CCH + kc + seg * 8);
        CP16(base + 10240 + off, wlg + (size_t)row * CCH + kc + seg * 8);
    }
    {
        int row = tid >> 3, seg = tid & 7;
        uint32_t off = (uint32_t)(row * 72 + seg * 8) * 2;
        CP16(base + 20480 + off, xhb + (size_t)(kc + row) * WID + j0 + seg * 8);
        CP16(base + 25088 + off, xlb + (size_t)(kc + row) * WID + j0 + seg * 8);
    }
}

__global__ __launch_bounds__(256, 2)
void qkv_gemm_mma()
{
    extern __shared__ char smem[];

    const int nt = blockIdx.x;        // 0..63
    const int my = blockIdx.y;        // 0..5
    const int b  = blockIdx.z;        // 0..7
    const int g  = my >> 1;
    const int m0g = (my & 1) * 128;
    const int j0 = nt * 64;

    const __half* whg = g_wh + (size_t)g * CCH * CCH + (size_t)m0g * CCH;
    const __half* wlg = g_wl + (size_t)g * CCH * CCH + (size_t)m0g * CCH;
    const __half* xhb = g_xh + (size_t)b * CCH * WID;
    const __half* xlb = g_xl + (size_t)b * CCH * WID;

    const int tid  = threadIdx.x;
    const int lane = tid & 31;
    const int wid  = tid >> 5;
    const int wm   = wid >> 1;        // 0..3 (32-row slabs)
    const int wn   = wid & 1;         // 0..1 (32-col slabs)
    const int ltt  = lane >> 3;
    const int ltr  = lane & 7;

    float acc[2][4][4];
    uint32_t dlo[2][4][2];
    #pragma unroll
    for (int i = 0; i < 2; ++i)
        #pragma unroll
        for (int j = 0; j < 4; ++j) {
            #pragma unroll
            for (int r = 0; r < 4; ++r) acc[i][j][r] = 0.f;
            dlo[i][j][0] = 0u; dlo[i][j][1] = 0u;
        }

    prefetch(smem, 0, tid, whg, wlg, xhb, xlb, 0, j0);
    CP_COMMIT();

    #pragma unroll 1
    for (int kc8 = 0; kc8 < 8; ++kc8) {
        const int stage = kc8 & 1;
        if (kc8 < 7) {
            prefetch(smem, stage ^ 1, tid, whg, wlg, xhb, xlb, (kc8 + 1) * 32, j0);
            CP_COMMIT();
            CP_WAIT(1);
        } else {
            CP_WAIT(0);
        }
        __syncthreads();

        const char* sb = smem + stage * STAGE_BYTES;
        const __half* Ahp = (const __half*)(sb);
        const __half* Alp = (const __half*)(sb + 10240);
        const __half* Bhp = (const __half*)(sb + 20480);
        const __half* Blp = (const __half*)(sb + 25088);

        #pragma unroll
        for (int ks = 0; ks < 2; ++ks) {
            const int kb = ks * 16;
            uint32_t bh[4][2], bl[4][2];
            #pragma unroll
            for (int np = 0; np < 2; ++np) {
                int krow = kb + (ltt & 1) * 8 + ltr;
                int ncol = wn * 32 + np * 16 + (ltt >> 1) * 8;
                ldsm_x4_t(sptr(Bhp + krow * 72 + ncol),
                          bh[np * 2][0], bh[np * 2][1],
                          bh[np * 2 + 1][0], bh[np * 2 + 1][1]);
                ldsm_x4_t(sptr(Blp + krow * 72 + ncol),
                          bl[np * 2][0], bl[np * 2][1],
                          bl[np * 2 + 1][0], bl[np * 2 + 1][1]);
            }
            uint32_t ah[2][4], al[2][4];
            #pragma unroll
            for (int ma = 0; ma < 2; ++ma) {
                int row = wm * 32 + ma * 16 + (ltt & 1) * 8 + ltr;
                int col = kb + (ltt >> 1) * 8;
                ldsm_x4(sptr(Ahp + row * 40 + col), ah[ma]);
                ldsm_x4(sptr(Alp + row * 40 + col), al[ma]);
            }
            // main pass: fp32 accumulate
            #pragma unroll
            for (int ma = 0; ma < 2; ++ma)
                #pragma unroll
                for (int na = 0; na < 4; ++na)
                    mma_f32(acc[ma][na], ah[ma], bh[na][0], bh[na][1]);
            // cross passes: fp16 accumulate (2x rate), pass-major for independence
            #pragma unroll
            for (int ma = 0; ma < 2; ++ma)
                #pragma unroll
                for (int na = 0; na < 4; ++na)
                    mma_f16(dlo[ma][na], al[ma], bh[na][0], bh[na][1]);
            #pragma unroll
            for (int ma = 0; ma < 2; ++ma)
                #pragma unroll
                for (int na = 0; na < 4; ++na)
                    mma_f16(dlo[ma][na], ah[ma], bl[na][0], bl[na][1]);
        }
        __syncthreads();
    }

    // epilogue: fold fp16 cross accumulator into fp32, store
    #pragma unroll
    for (int ma = 0; ma < 2; ++ma) {
        int r0 = m0g + wm * 32 + ma * 16 + (lane >> 2);
        #pragma unroll
        for (int na = 0; na < 4; ++na) {
            __half2 c01 = *(__half2*)&dlo[ma][na][0];
            __half2 c23 = *(__half2*)&dlo[ma][na][1];
            float2 f01 = __half22float2(c01);
            float2 f23 = __half22float2(c23);
            int jj = j0 + wn * 32 + na * 8 + (lane & 3) * 2;
            float* d0 = g_qkv + ((size_t)(g * 256 + r0) * BATCH + b) * WID + jj;
            float* d1 = d0 + (size_t)8 * BATCH * WID;
            *(float2*)d0 = make_float2(acc[ma][na][0] + f01.x, acc[ma][na][1] + f01.y);
            *(float2*)d1 = make_float2(acc[ma][na][2] + f23.x, acc[ma][na][3] + f23.y);
        }
    }
}

// ---------------------------------------------------------------------------
// Kernel 2: windowed softmax, 8 outputs/thread
// ---------------------------------------------------------------------------
__global__ __launch_bounds__(256)
void attn_window8(float* __restrict__ out)
{
    int t8 = blockIdx.x * 256 + threadIdx.x;
    int w  = (t8 & 511) * 8;
    int t  = t8 >> 9;
    int o  = t & 255;
    int b  = t >> 8;

    const float* Q = g_qkv + ((size_t)o * BATCH + b) * WID;
    const float* K = Q + (size_t)256 * BATCH * WID;
    const float* V = Q + (size_t)512 * BATCH * WID;

    const float4 z4 = make_float4(0.f, 0.f, 0.f, 0.f);
    float4 q0 = *(const float4*)(Q + w);
    float4 q1 = *(const float4*)(Q + w + 4);
    float4 km = (w >= 4)      ? *(const float4*)(K + w - 4) : z4;
    float4 k0 = *(const float4*)(K + w);
    float4 k1 = *(const float4*)(K + w + 4);
    float4 kp = (w + 8 < WID) ? *(const float4*)(K + w + 8) : z4;
    float4 vm = (w >= 4)      ? *(const float4*)(V + w - 4) : z4;
    float4 v0 = *(const float4*)(V + w);
    float4 v1 = *(const float4*)(V + w + 4);
    float4 vp = (w + 8 < WID) ? *(const float4*)(V + w + 8) : z4;

    float kk[14] = {km.y, km.z, km.w, k0.x, k0.y, k0.z, k0.w,
                    k1.x, k1.y, k1.z, k1.w, kp.x, kp.y, kp.z};
    float vv[14] = {vm.y, vm.z, vm.w, v0.x, v0.y, v0.z, v0.w,
                    v1.x, v1.y, v1.z, v1.w, vp.x, vp.y, vp.z};
    float qv[8]  = {q0.x, q0.y, q0.z, q0.w, q1.x, q1.y, q1.z, q1.w};

    float res[8];
    #pragma unroll
    for (int tt = 0; tt < 8; ++tt) {
        float s[7];
        float m = -1e30f;
        #pragma unroll
        for (int i = 0; i < 7; ++i) {
            s[i] = qv[tt] * kk[tt + i];
            m = fmaxf(m, s[i]);
        }
        float sum = 0.f, accn = 0.f;
        #pragma unroll
        for (int i = 0; i < 7; ++i) {
            float e = __expf(s[i] - m);
            sum += e;
            accn = fmaf(e, vv[tt + i], accn);
        }
        res[tt] = accn / sum;
    }
    float* dst = out + (size_t)t * WID + w;
    *(float4*)dst       = make_float4(res[0], res[1], res[2], res[3]);
    *(float4*)(dst + 4) = make_float4(res[4], res[5], res[6], res[7]);
}

// ---------------------------------------------------------------------------
extern "C" void kernel_launch(void* const* d_in, const int* in_sizes, int n_in,
                              void* d_out, int out_size)
{
    (void)in_sizes; (void)n_in; (void)out_size;
    const float* x  = (const float*)d_in[0];
    const float* wq = (const float*)d_in[1];
    const float* wk = (const float*)d_in[2];
    const float* wv = (const float*)d_in[3];
    float* out = (float*)d_out;

    cudaFuncSetAttribute(qkv_gemm_mma, cudaFuncAttributeMaxDynamicSharedMemorySize, SMEM_GEMM);

    convert_split<<<(NX4 + 3 * NW4 + 255) / 256, 256>>>(x, wq, wk, wv);

    dim3 grid(64, 6, 8);
    qkv_gemm_mma<<<grid, 256, SMEM_GEMM>>>();

    attn_window8<<<(BATCH * CCH * WID) / (256 * 8), 256>>>(out);
}